// round 5
// baseline (speedup 1.0000x reference)
#include <cuda_runtime.h>

// Problem dims
#define B  64
#define L  1024
#define D  64
#define H  512
#define LN_EPS 1e-5f

// Partitioning: 8 batch-groups x 16 j-slices = 128 CTAs
#define GB 8     // batch groups
#define GJ 16    // hidden-column slices
#define BC 8     // batches per CTA   (B / GB)
#define JC 32    // j columns per CTA (H / GJ)
#define KG 4     // k-groups (threads split the 512 k-dim 4 ways)
#define NT 128   // threads per CTA = JC * KG

// SMEM: Whh [3][128 k4][JC] float4  +  h_s [BC][H] float  +  red [4][BC][JC][KG] float
#define WHH_F4   (3 * 128 * JC)                    // 12288 float4 = 196608 B
#define SMEM_BYTES (WHH_F4 * 16 + BC * H * 4 + 4 * BC * JC * KG * 4)   // 229376 B

// Global scratch (static — no allocations allowed)
__device__ float g_h[2][B * H];   // ping-pong hidden state
__device__ int   g_cnt[GB];       // per-group monotonic barrier counters

// ---------------- packed f32x2 helpers ----------------
__device__ __forceinline__ void ffma2(unsigned long long& acc,
                                      unsigned long long a, unsigned long long b) {
    asm("fma.rn.f32x2 %0, %1, %2, %0;" : "+l"(acc) : "l"(a), "l"(b));
}
__device__ __forceinline__ unsigned long long pk2(float lo, float hi) {
    unsigned long long r;
    asm("mov.b64 %0, {%1, %2};" : "=l"(r) : "f"(lo), "f"(hi));
    return r;
}
__device__ __forceinline__ float upk_sum(unsigned long long v) {
    float lo, hi;
    asm("mov.b64 {%0, %1}, %2;" : "=f"(lo), "=f"(hi) : "l"(v));
    return lo + hi;
}

__global__ void init_kernel() {
    if (threadIdx.x < GB) g_cnt[threadIdx.x] = 0;
}

// ---------------- persistent recurrent kernel ----------------
__global__ void __launch_bounds__(NT, 1)
gru_kernel(const float* __restrict__ x,     // (B, L, D)
           const float* __restrict__ h0,    // (1, B, H)
           const float* __restrict__ W_ih,  // (3H, D)
           const float* __restrict__ W_hh,  // (3H, H)
           const float* __restrict__ b_ih,  // (3H)
           const float* __restrict__ b_hh,  // (3H)
           float* __restrict__ out_hseq,    // (B, L, H) — raw h, LN'd later in place
           float* __restrict__ out_hN)      // (1, B, H)
{
    extern __shared__ float4 smem[];
    float4* Whh_s = smem;                              // [3][128][JC] float4
    float*  h_s   = (float*)(smem + WHH_F4);           // [BC][H]
    float*  red   = h_s + BC * H;                      // [4][BC][JC][KG]

    const int tid = threadIdx.x;
    const int j   = tid & 31;        // lane = hidden column within slice
    const int kg  = tid >> 5;        // k-group (0..3), k-slice = 128
    const int grp = blockIdx.x / GJ; // batch group
    const int slc = blockIdx.x % GJ; // j slice
    const int jg  = slc * JC + j;    // global hidden column
    const int bg0 = grp * BC;        // first global batch

    // ---- load W_hh slice into SMEM (once) ----
    // 96 rows (3 gates x 32 j) of 512 floats; warp-coalesced float4 loads.
    for (int rbase = 0; rbase < 96; rbase += 4) {
        int r  = rbase + kg;
        int g  = r >> 5;
        int jr = r & 31;
        const float4* src = (const float4*)(W_hh + ((size_t)(g * H + slc * JC + jr)) * H);
        #pragma unroll
        for (int c = 0; c < 4; c++) {
            int k4 = j + c * 32;
            Whh_s[(g * 128 + k4) * JC + jr] = src[k4];
        }
    }

    // ---- W_ih slice into registers (packed f32x2) ----
    unsigned long long wih[3][8];
    #pragma unroll
    for (int g = 0; g < 3; g++) {
        const unsigned long long* src =
            (const unsigned long long*)(W_ih + (size_t)(g * H + jg) * D + kg * 16);
        #pragma unroll
        for (int i = 0; i < 8; i++) wih[g][i] = src[i];
    }

    // ---- biases for finalize (this thread's j column) ----
    const float bsr  = b_ih[jg]         + b_hh[jg];
    const float bsz  = b_ih[H + jg]     + b_hh[H + jg];
    const float bin_ = b_ih[2 * H + jg];
    const float bhn  = b_hh[2 * H + jg];

    // ---- stage initial h (from h0 input) ----
    {
        const float4* src = (const float4*)(h0 + (size_t)bg0 * H);
        float4* dst = (float4*)h_s;
        #pragma unroll
        for (int i = 0; i < 8; i++) dst[tid + i * NT] = src[tid + i * NT];
    }
    __syncthreads();

    for (int t = 0; t < L; t++) {
        // accumulators (packed pairs); zero bits == {0.f, 0.f}
        unsigned long long ar[BC], az[BC], ain[BC], ahn[BC];
        #pragma unroll
        for (int b = 0; b < BC; b++) { ar[b] = 0; az[b] = 0; ain[b] = 0; ahn[b] = 0; }

        // ---- input projection part (k-slice of D) ----
        #pragma unroll
        for (int b = 0; b < BC; b++) {
            const unsigned long long* xp =
                (const unsigned long long*)(x + ((size_t)(bg0 + b) * L + t) * D + kg * 16);
            #pragma unroll
            for (int i = 0; i < 8; i++) {
                unsigned long long xv = xp[i];
                ffma2(ar[b],  wih[0][i], xv);
                ffma2(az[b],  wih[1][i], xv);
                ffma2(ain[b], wih[2][i], xv);
            }
        }

        // ---- recurrent part: weights reused across 8 batches ----
        const int kb4 = kg * 32;
        #pragma unroll 4
        for (int k4 = 0; k4 < 32; k4++) {
            const ulonglong2 wr = *(const ulonglong2*)&Whh_s[(0 * 128 + kb4 + k4) * JC + j];
            const ulonglong2 wz = *(const ulonglong2*)&Whh_s[(1 * 128 + kb4 + k4) * JC + j];
            const ulonglong2 wn = *(const ulonglong2*)&Whh_s[(2 * 128 + kb4 + k4) * JC + j];
            #pragma unroll
            for (int b = 0; b < BC; b++) {
                const ulonglong2 hv = *(const ulonglong2*)&h_s[b * H + (kb4 + k4) * 4];
                ffma2(ar[b],  wr.x, hv.x);  ffma2(ar[b],  wr.y, hv.y);
                ffma2(az[b],  wz.x, hv.x);  ffma2(az[b],  wz.y, hv.y);
                ffma2(ahn[b], wn.x, hv.x);  ffma2(ahn[b], wn.y, hv.y);
            }
        }

        // ---- write per-kg partials ----
        #pragma unroll
        for (int b = 0; b < BC; b++) {
            red[((0 * BC + b) * JC + j) * KG + kg] = upk_sum(ar[b]);
            red[((1 * BC + b) * JC + j) * KG + kg] = upk_sum(az[b]);
            red[((2 * BC + b) * JC + j) * KG + kg] = upk_sum(ahn[b]);
            red[((3 * BC + b) * JC + j) * KG + kg] = upk_sum(ain[b]);
        }
        __syncthreads();

        // ---- finalize: 2 (b, j) pairs per thread ----
        const int wbuf = t & 1;
        float* gdst = g_h[wbuf];
        #pragma unroll
        for (int pp = 0; pp < 2; pp++) {
            int b = (tid >> 5) + pp * 4;
            float4 v;
            v = *(const float4*)&red[((0 * BC + b) * JC + j) * KG];
            float sr = v.x + v.y + v.z + v.w;
            v = *(const float4*)&red[((1 * BC + b) * JC + j) * KG];
            float sz = v.x + v.y + v.z + v.w;
            v = *(const float4*)&red[((2 * BC + b) * JC + j) * KG];
            float shn = v.x + v.y + v.z + v.w;
            v = *(const float4*)&red[((3 * BC + b) * JC + j) * KG];
            float sin_ = v.x + v.y + v.z + v.w;

            float r = 1.f / (1.f + __expf(-(sr + bsr)));
            float z = 1.f / (1.f + __expf(-(sz + bsz)));
            float n = tanhf(sin_ + bin_ + r * (shn + bhn));
            float hold = h_s[b * H + jg];
            float hnew = (1.f - z) * n + z * hold;

            int bglob = bg0 + b;
            gdst[(size_t)bglob * H + jg] = hnew;
            out_hseq[((size_t)bglob * L + t) * H + jg] = hnew;
            if (t == L - 1) out_hN[(size_t)bglob * H + jg] = hnew;
        }

        // ---- group barrier (release) ----
        __threadfence();
        __syncthreads();
        if (tid == 0) atomicAdd(&g_cnt[grp], 1);

        if (t + 1 < L) {
            if (tid == 0) {
                const int target = GJ * (t + 1);
                int c;
                do {
                    asm volatile("ld.acquire.gpu.global.b32 %0, [%1];"
                                 : "=r"(c) : "l"(&g_cnt[grp]) : "memory");
                } while (c < target);
            }
            __syncthreads();
            // restage h(t) from the buffer just written by the whole group
            const float4* src = (const float4*)(g_h[wbuf] + (size_t)bg0 * H);
            float4 tmp[8];
            #pragma unroll
            for (int i = 0; i < 8; i++) tmp[i] = src[tid + i * NT];
            #pragma unroll
            for (int i = 0; i < 8; i++) ((float4*)h_s)[tid + i * NT] = tmp[i];
            __syncthreads();
        }
    }
}

// ---------------- LayerNorm (in place) + prediction GEMM ----------------
__global__ void __launch_bounds__(128)
ln_pred_kernel(const float* __restrict__ gamma, const float* __restrict__ beta,
               const float* __restrict__ Wp,    const float* __restrict__ bp,
               float* __restrict__ hseq,        float* __restrict__ xhat)
{
    __shared__ float sh[H];
    __shared__ float redu[8];

    const int row = blockIdx.x;          // b * L + t
    const int tid = threadIdx.x;
    float* hp = hseq + (size_t)row * H;

    float4 v = ((const float4*)hp)[tid];
    float s = v.x + v.y + v.z + v.w;
    float q = v.x * v.x + v.y * v.y + v.z * v.z + v.w * v.w;
    #pragma unroll
    for (int o = 16; o; o >>= 1) {
        s += __shfl_xor_sync(0xffffffffu, s, o);
        q += __shfl_xor_sync(0xffffffffu, q, o);
    }
    if ((tid & 31) == 0) { redu[tid >> 5] = s; redu[4 + (tid >> 5)] = q; }
    __syncthreads();
    if (tid == 0) {
        float S = redu[0] + redu[1] + redu[2] + redu[3];
        float Q = redu[4] + redu[5] + redu[6] + redu[7];
        float mu = S * (1.f / H);
        float var = Q * (1.f / H) - mu * mu;
        redu[0] = mu;
        redu[1] = rsqrtf(var + LN_EPS);
    }
    __syncthreads();
    const float mu = redu[0], rs = redu[1];

    float4 g4 = ((const float4*)gamma)[tid];
    float4 b4 = ((const float4*)beta)[tid];
    float4 o;
    o.x = (v.x - mu) * rs * g4.x + b4.x;
    o.y = (v.y - mu) * rs * g4.y + b4.y;
    o.z = (v.z - mu) * rs * g4.z + b4.z;
    o.w = (v.w - mu) * rs * g4.w + b4.w;
    ((float4*)hp)[tid] = o;     // in-place normalized h_seq
    ((float4*)sh)[tid] = o;
    __syncthreads();

    // prediction: warp w computes outputs j = w*16 .. w*16+15
    const int w = tid >> 5, l = tid & 31;
    float* xo = xhat + (size_t)row * D;
    for (int jj = 0; jj < 16; jj++) {
        int jo = w * 16 + jj;
        const float4* wp4 = (const float4*)(Wp + (size_t)jo * H);
        float acc = 0.f;
        #pragma unroll
        for (int k4 = 0; k4 < 4; k4++) {
            float4 wv = wp4[k4 * 32 + l];
            float4 hv = ((const float4*)sh)[k4 * 32 + l];
            acc += wv.x * hv.x + wv.y * hv.y + wv.z * hv.z + wv.w * hv.w;
        }
        #pragma unroll
        for (int o2 = 16; o2; o2 >>= 1) acc += __shfl_xor_sync(0xffffffffu, acc, o2);
        if (l == 0) xo[jo] = acc + bp[jo];
    }
}

extern "C" void kernel_launch(void* const* d_in, const int* in_sizes, int n_in,
                              void* d_out, int out_size)
{
    const float* x      = (const float*)d_in[0];
    const float* h0     = (const float*)d_in[1];
    const float* W_ih   = (const float*)d_in[2];
    const float* W_hh   = (const float*)d_in[3];
    const float* b_ih   = (const float*)d_in[4];
    const float* b_hh   = (const float*)d_in[5];
    const float* gamma  = (const float*)d_in[6];
    const float* beta   = (const float*)d_in[7];
    const float* W_pred = (const float*)d_in[8];
    const float* b_pred = (const float*)d_in[9];

    float* out      = (float*)d_out;
    float* out_hseq = out;                                   // (B, L, H)
    float* out_hN   = out + (size_t)B * L * H;               // (1, B, H)
    float* out_xhat = out_hN + (size_t)B * H;                // (B, L, D)

    cudaFuncSetAttribute(gru_kernel, cudaFuncAttributeMaxDynamicSharedMemorySize,
                         SMEM_BYTES);

    init_kernel<<<1, 32>>>();
    gru_kernel<<<GB * GJ, NT, SMEM_BYTES>>>(x, h0, W_ih, W_hh, b_ih, b_hh,
                                            out_hseq, out_hN);
    ln_pred_kernel<<<B * L, 128>>>(gamma, beta, W_pred, b_pred, out_hseq, out_xhat);
}

// round 6
// speedup vs baseline: 1.1569x; 1.1569x over previous
#include <cuda_runtime.h>

// Problem dims
#define B  64
#define L  1024
#define D  64
#define H  512
#define LN_EPS 1e-5f

// Partitioning: 8 batch-groups x 16 j-slices = 128 CTAs
#define GB 8     // batch groups
#define GJ 16    // hidden-column slices
#define BC 8     // batches per CTA   (B / GB)
#define JC 32    // j columns per CTA (H / GJ)
#define KG 8     // k-groups (threads split the 512 k-dim 8 ways)
#define NT 256   // threads per CTA = JC * KG

// SMEM: Whh [3][128 k4][JC] float4  +  h_s [BC][H] float  +  red [4][BC][4][JC] float
#define WHH_F4     (3 * 128 * JC)                 // 12288 float4 = 196608 B
#define RED_F      (4 * BC * 4 * JC)              // 4096 floats  = 16384 B
#define SMEM_BYTES (WHH_F4 * 16 + BC * H * 4 + RED_F * 4)   // 229376 B

typedef unsigned long long ull;

// Global scratch (static — no allocations allowed)
__device__ float g_h[2][B * H];   // ping-pong hidden state
__device__ int   g_cnt[GB];      // per-group monotonic barrier counters
__device__ int   g_done[GB];     // exit counters (for counter reset)

// ---------------- packed f32x2 helpers ----------------
__device__ __forceinline__ void ffma2(ull& acc, ull a, ull b) {
    asm("fma.rn.f32x2 %0, %1, %2, %0;" : "+l"(acc) : "l"(a), "l"(b));
}
__device__ __forceinline__ float upk_sum(ull v) {
    float lo, hi;
    asm("mov.b64 {%0, %1}, %2;" : "=f"(lo), "=f"(hi) : "l"(v));
    return lo + hi;
}

// ---------------- persistent recurrent kernel ----------------
__global__ void __launch_bounds__(NT, 1)
gru_kernel(const float* __restrict__ x,     // (B, L, D)
           const float* __restrict__ h0,    // (1, B, H)
           const float* __restrict__ W_ih,  // (3H, D)
           const float* __restrict__ W_hh,  // (3H, H)
           const float* __restrict__ b_ih,  // (3H)
           const float* __restrict__ b_hh,  // (3H)
           float* __restrict__ out_hseq,    // (B, L, H) — raw h, LN'd later in place
           float* __restrict__ out_hN)      // (1, B, H)
{
    extern __shared__ float4 smem[];
    float4* Whh_s = smem;                              // [3][128][JC] float4
    float*  h_s   = (float*)(smem + WHH_F4);           // [BC][H]
    float*  red   = h_s + BC * H;                      // [4 gates][BC][4][JC]

    const int tid = threadIdx.x;
    const int j   = tid & 31;        // lane = hidden column within slice
    const int kg  = tid >> 5;        // k-group (0..7), k-slice = 64
    const int grp = blockIdx.x / GJ; // batch group
    const int slc = blockIdx.x % GJ; // j slice
    const int jg  = slc * JC + j;    // global hidden column
    const int bg0 = grp * BC;        // first global batch

    // ---- load W_hh slice into SMEM (once) ----
    for (int rbase = 0; rbase < 96; rbase += 8) {
        int r  = rbase + kg;
        int g  = r >> 5;
        int jr = r & 31;
        const float4* src = (const float4*)(W_hh + ((size_t)(g * H + slc * JC + jr)) * H);
        #pragma unroll
        for (int c = 0; c < 4; c++) {
            int k4 = j + c * 32;
            Whh_s[(g * 128 + k4) * JC + jr] = src[k4];
        }
    }

    // ---- W_ih slice into registers (packed f32x2): 8 floats of D per kg ----
    ull wih[3][4];
    #pragma unroll
    for (int g = 0; g < 3; g++) {
        const ull* src = (const ull*)(W_ih + (size_t)(g * H + jg) * D) + kg * 4;
        #pragma unroll
        for (int i = 0; i < 4; i++) wih[g][i] = src[i];
    }

    // ---- biases for finalize (this thread's j column) ----
    const float bsr  = b_ih[jg]         + b_hh[jg];
    const float bsz  = b_ih[H + jg]     + b_hh[H + jg];
    const float bin_ = b_ih[2 * H + jg];
    const float bhn  = b_hh[2 * H + jg];

    // ---- stage initial h ----
    {
        const float4* src = (const float4*)(h0 + (size_t)bg0 * H);
        float4* dst = (float4*)h_s;
        #pragma unroll
        for (int i = 0; i < 4; i++) dst[tid + i * NT] = src[tid + i * NT];
    }

    // ---- input projection for t=0 ----
    ull giR[BC], giZ[BC], giN[BC];
    #define COMPUTE_GI(tt) do {                                                  \
        _Pragma("unroll")                                                        \
        for (int b = 0; b < BC; b++) {                                           \
            const ull* xp = (const ull*)(x + ((size_t)(bg0 + b) * L + (tt)) * D) \
                            + kg * 4;                                            \
            ull x0 = xp[0], x1 = xp[1], x2 = xp[2], x3 = xp[3];                  \
            giR[b] = 0; giZ[b] = 0; giN[b] = 0;                                  \
            ffma2(giR[b], wih[0][0], x0); ffma2(giR[b], wih[0][1], x1);          \
            ffma2(giR[b], wih[0][2], x2); ffma2(giR[b], wih[0][3], x3);          \
            ffma2(giZ[b], wih[1][0], x0); ffma2(giZ[b], wih[1][1], x1);          \
            ffma2(giZ[b], wih[1][2], x2); ffma2(giZ[b], wih[1][3], x3);          \
            ffma2(giN[b], wih[2][0], x0); ffma2(giN[b], wih[2][1], x1);          \
            ffma2(giN[b], wih[2][2], x2); ffma2(giN[b], wih[2][3], x3);          \
        }                                                                        \
    } while (0)
    COMPUTE_GI(0);

    __syncthreads();

    for (int t = 0; t < L; t++) {
        // ---- recurrent GEMM: seed accumulators with gi ----
        ull ar[BC], az[BC], an_[BC], ahn[BC];
        #pragma unroll
        for (int b = 0; b < BC; b++) {
            ar[b] = giR[b]; az[b] = giZ[b]; an_[b] = giN[b]; ahn[b] = 0;
        }

        const int kb = kg * 16;
        #pragma unroll 4
        for (int k4m = 0; k4m < 16; k4m++) {
            const int k4 = kb + k4m;
            const ulonglong2 wr = *(const ulonglong2*)&Whh_s[(0 * 128 + k4) * JC + j];
            const ulonglong2 wz = *(const ulonglong2*)&Whh_s[(1 * 128 + k4) * JC + j];
            const ulonglong2 wn = *(const ulonglong2*)&Whh_s[(2 * 128 + k4) * JC + j];
            #pragma unroll
            for (int b = 0; b < BC; b++) {
                const ulonglong2 hv = *(const ulonglong2*)&h_s[b * H + k4 * 4];
                ffma2(ar[b],  wr.x, hv.x);  ffma2(ar[b],  wr.y, hv.y);
                ffma2(az[b],  wz.x, hv.x);  ffma2(az[b],  wz.y, hv.y);
                ffma2(ahn[b], wn.x, hv.x);  ffma2(ahn[b], wn.y, hv.y);
            }
        }

        // ---- two-phase cross-kg reduction in SMEM ----
        const int kgm = kg & 3;
        if (kg >= 4) {
            #pragma unroll
            for (int b = 0; b < BC; b++) {
                red[((0 * BC + b) * 4 + kgm) * JC + j] = upk_sum(ar[b]);
                red[((1 * BC + b) * 4 + kgm) * JC + j] = upk_sum(az[b]);
                red[((2 * BC + b) * 4 + kgm) * JC + j] = upk_sum(ahn[b]);
                red[((3 * BC + b) * 4 + kgm) * JC + j] = upk_sum(an_[b]);
            }
        }
        __syncthreads();
        if (kg < 4) {
            #pragma unroll
            for (int b = 0; b < BC; b++) {
                red[((0 * BC + b) * 4 + kgm) * JC + j] += upk_sum(ar[b]);
                red[((1 * BC + b) * 4 + kgm) * JC + j] += upk_sum(az[b]);
                red[((2 * BC + b) * 4 + kgm) * JC + j] += upk_sum(ahn[b]);
                red[((3 * BC + b) * 4 + kgm) * JC + j] += upk_sum(an_[b]);
            }
        }
        __syncthreads();

        // ---- finalize: exactly one (b=kg, j=lane) pair per thread ----
        {
            const int b = kg;
            float sr = 0.f, sz = 0.f, shn = 0.f, sn = 0.f;
            #pragma unroll
            for (int c = 0; c < 4; c++) {
                sr  += red[((0 * BC + b) * 4 + c) * JC + j];
                sz  += red[((1 * BC + b) * 4 + c) * JC + j];
                shn += red[((2 * BC + b) * 4 + c) * JC + j];
                sn  += red[((3 * BC + b) * 4 + c) * JC + j];
            }
            float r = 1.f / (1.f + __expf(-(sr + bsr)));
            float z = 1.f / (1.f + __expf(-(sz + bsz)));
            float n = tanhf(sn + bin_ + r * (shn + bhn));
            float hold = h_s[b * H + jg];
            float hnew = fmaf(z, hold - n, n);   // (1-z)n + z*h

            const int bglob = bg0 + b;
            g_h[t & 1][(size_t)bglob * H + jg] = hnew;
            out_hseq[((size_t)bglob * L + t) * H + jg] = hnew;
            if (t == L - 1) out_hN[(size_t)bglob * H + jg] = hnew;
        }

        __syncthreads();   // all STGs + red reads + h_s reads complete

        if (t + 1 < L) {
            // release-arrive (orders all CTA threads' prior STGs via bar+release chain)
            if (tid == 0) {
                asm volatile("red.release.gpu.global.add.u32 [%0], 1;"
                             :: "l"(&g_cnt[grp]) : "memory");
            }
            // input projection for t+1 — hidden behind other CTAs' tails
            COMPUTE_GI(t + 1);

            if (tid == 0) {
                const int target = GJ * (t + 1);
                int c;
                do {
                    asm volatile("ld.acquire.gpu.global.b32 %0, [%1];"
                                 : "=r"(c) : "l"(&g_cnt[grp]) : "memory");
                } while (c < target);
            }
            __syncthreads();
            // restage h(t) for the whole batch group
            const float4* src = (const float4*)(g_h[t & 1] + (size_t)bg0 * H);
            float4* dst = (float4*)h_s;
            #pragma unroll
            for (int i = 0; i < 4; i++) dst[tid + i * NT] = src[tid + i * NT];
            __syncthreads();
        }
    }

    // ---- exit protocol: reset counters for next graph replay ----
    if (tid == 0) {
        asm volatile("red.release.gpu.global.add.u32 [%0], 1;"
                     :: "l"(&g_done[grp]) : "memory");
        if (slc == 0) {
            int c;
            do {
                asm volatile("ld.acquire.gpu.global.b32 %0, [%1];"
                             : "=r"(c) : "l"(&g_done[grp]) : "memory");
            } while (c < GJ);
            atomicExch(&g_cnt[grp], 0);
            atomicExch(&g_done[grp], 0);
        }
    }
}

// ---------------- LayerNorm (in place) + prediction GEMM ----------------
__global__ void __launch_bounds__(128)
ln_pred_kernel(const float* __restrict__ gamma, const float* __restrict__ beta,
               const float* __restrict__ Wp,    const float* __restrict__ bp,
               float* __restrict__ hseq,        float* __restrict__ xhat)
{
    __shared__ float sh[H];
    __shared__ float redu[8];

    const int row = blockIdx.x;          // b * L + t
    const int tid = threadIdx.x;
    float* hp = hseq + (size_t)row * H;

    float4 v = ((const float4*)hp)[tid];
    float s = v.x + v.y + v.z + v.w;
    float q = v.x * v.x + v.y * v.y + v.z * v.z + v.w * v.w;
    #pragma unroll
    for (int o = 16; o; o >>= 1) {
        s += __shfl_xor_sync(0xffffffffu, s, o);
        q += __shfl_xor_sync(0xffffffffu, q, o);
    }
    if ((tid & 31) == 0) { redu[tid >> 5] = s; redu[4 + (tid >> 5)] = q; }
    __syncthreads();
    if (tid == 0) {
        float S = redu[0] + redu[1] + redu[2] + redu[3];
        float Q = redu[4] + redu[5] + redu[6] + redu[7];
        float mu = S * (1.f / H);
        float var = Q * (1.f / H) - mu * mu;
        redu[0] = mu;
        redu[1] = rsqrtf(var + LN_EPS);
    }
    __syncthreads();
    const float mu = redu[0], rs = redu[1];

    float4 g4 = ((const float4*)gamma)[tid];
    float4 b4 = ((const float4*)beta)[tid];
    float4 o;
    o.x = (v.x - mu) * rs * g4.x + b4.x;
    o.y = (v.y - mu) * rs * g4.y + b4.y;
    o.z = (v.z - mu) * rs * g4.z + b4.z;
    o.w = (v.w - mu) * rs * g4.w + b4.w;
    ((float4*)hp)[tid] = o;     // in-place normalized h_seq
    ((float4*)sh)[tid] = o;
    __syncthreads();

    // prediction: warp w computes outputs j = w*16 .. w*16+15
    const int w = tid >> 5, l = tid & 31;
    float* xo = xhat + (size_t)row * D;
    for (int jj = 0; jj < 16; jj++) {
        int jo = w * 16 + jj;
        const float4* wp4 = (const float4*)(Wp + (size_t)jo * H);
        float acc = 0.f;
        #pragma unroll
        for (int k4 = 0; k4 < 4; k4++) {
            float4 wv = wp4[k4 * 32 + l];
            float4 hv = ((const float4*)sh)[k4 * 32 + l];
            acc += wv.x * hv.x + wv.y * hv.y + wv.z * hv.z + wv.w * hv.w;
        }
        #pragma unroll
        for (int o2 = 16; o2; o2 >>= 1) acc += __shfl_xor_sync(0xffffffffu, acc, o2);
        if (l == 0) xo[jo] = acc + bp[jo];
    }
}

extern "C" void kernel_launch(void* const* d_in, const int* in_sizes, int n_in,
                              void* d_out, int out_size)
{
    const float* x      = (const float*)d_in[0];
    const float* h0     = (const float*)d_in[1];
    const float* W_ih   = (const float*)d_in[2];
    const float* W_hh   = (const float*)d_in[3];
    const float* b_ih   = (const float*)d_in[4];
    const float* b_hh   = (const float*)d_in[5];
    const float* gamma  = (const float*)d_in[6];
    const float* beta   = (const float*)d_in[7];
    const float* W_pred = (const float*)d_in[8];
    const float* b_pred = (const float*)d_in[9];

    float* out      = (float*)d_out;
    float* out_hseq = out;                                   // (B, L, H)
    float* out_hN   = out + (size_t)B * L * H;               // (1, B, H)
    float* out_xhat = out_hN + (size_t)B * H;                // (B, L, D)

    cudaFuncSetAttribute(gru_kernel, cudaFuncAttributeMaxDynamicSharedMemorySize,
                         SMEM_BYTES);

    gru_kernel<<<GB * GJ, NT, SMEM_BYTES>>>(x, h0, W_ih, W_hh, b_ih, b_hh,
                                            out_hseq, out_hN);
    ln_pred_kernel<<<B * L, 128>>>(gamma, beta, W_pred, b_pred, out_hseq, out_xhat);
}